// round 9
// baseline (speedup 1.0000x reference)
#include <cuda_runtime.h>

// CapsuleLayer dynamic routing, algebraically collapsed:
//   b[n,m] = x[n,:] @ Pacc[:,m]   (Pacc accumulates log2e * W@v across iterations)
//   s[m,:] = (1/Z) (e^T x) W[:,m,:],  v = squash(s),  Pacc[:,m] += log2e*W[:,m,:] v
// u_hat (268MB) never materialized. Softmax stabilized by Cauchy-Schwarz bound
// |l| <= max_n||x_n|| * ||Pacc_col||, in log2 domain so exp = single EX2.
// R9: 768 threads / 24 warps (6 per SMSP, 85 regs) — C=2, 8 cap-pair groups x
//     3 row chunks. Same pipe work as the 27us plateau shape, +50% warps to
//     cover the LDS->FMA->EX2 latency chains.

#define NROW    2048
#define DIN     16
#define XSTRIDE 20
#define THREADS 768
#define LOG2E   1.4426950408889634f

typedef unsigned long long ull;

struct Smem {
  float xs[NROW * XSTRIDE];     // padded x rows (conflict-free stride 80B)
  float Wdc[16 * 16 * 16];      // [ml][d][c]
  float Wcd[16 * 16 * 16];      // [ml][c][d]
  float Pacc[16][16];           // [ml][d]  (scaled by log2e)
  float party[3][4][16][16];    // [chunk][lanegrp][ml][d]
  float partZ[3][4][16];        // [chunk][lanegrp][ml]
  float wpart[24][16];          // per-warp partial column sums of x
  float wmax[24];               // per-warp max row-norm^2
  float sumx[16];               // sum over n of x[n,d]
  float vbuf[16][16];           // [ml][c]
  float bnd[16];                // softmax shift bound per ml (log2 domain)
  float mxnorm;
  float pad[3];
};

__device__ __forceinline__ ull mul2(ull a, ull b) {
  ull d; asm("mul.rn.f32x2 %0, %1, %2;" : "=l"(d) : "l"(a), "l"(b)); return d;
}
__device__ __forceinline__ ull add2(ull a, ull b) {
  ull d; asm("add.rn.f32x2 %0, %1, %2;" : "=l"(d) : "l"(a), "l"(b)); return d;
}
__device__ __forceinline__ ull fma2(ull a, ull b, ull c) {
  ull d; asm("fma.rn.f32x2 %0, %1, %2, %3;" : "=l"(d) : "l"(a), "l"(b), "l"(c)); return d;
}
__device__ __forceinline__ ull pack2(float x) {
  ull d; asm("mov.b64 %0, {%1, %1};" : "=l"(d) : "f"(x)); return d;
}
__device__ __forceinline__ ull packlh(float lo, float hi) {
  ull d; asm("mov.b64 %0, {%1, %2};" : "=l"(d) : "f"(lo), "f"(hi)); return d;
}
__device__ __forceinline__ float hadd2(ull a) {
  float lo, hi; asm("mov.b64 {%0, %1}, %2;" : "=f"(lo), "=f"(hi) : "l"(a)); return lo + hi;
}
__device__ __forceinline__ float ex2f(float x) {
  float r; asm("ex2.approx.f32 %0, %1;" : "=f"(r) : "f"(x)); return r;
}

__global__ void __launch_bounds__(THREADS, 1)
caps_routing_kernel(const float* __restrict__ X, const float* __restrict__ Wg,
                    float* __restrict__ Y) {
  extern __shared__ char smraw[];
  Smem* sm = reinterpret_cast<Smem*>(smraw);
  const int tid  = threadIdx.x;
  const int lane = tid & 31;
  const int w    = tid >> 5;
  const int b    = blockIdx.x >> 1;
  const int m0   = (blockIdx.x & 1) * 16;

  if (tid < 256) ((float*)sm->Pacc)[tid] = 0.f;
  if (tid < 16)  sm->bnd[tid] = 0.f;

  // ---- Load x tile (128KB) into padded smem; fold in column sums + max row norm ----
  const float4* Xb = reinterpret_cast<const float4*>(X + (size_t)b * NROW * DIN);
  const int q = tid & 3;   // constant quarter per thread (stride 768 ≡ 0 mod 4)
  float4 s4 = make_float4(0.f, 0.f, 0.f, 0.f);
  float mloc = 0.f;
#pragma unroll 1
  for (int idx = tid; idx < NROW * 4; idx += THREADS) {
    int n = idx >> 2;
    float4 v = Xb[idx];
    *reinterpret_cast<float4*>(&sm->xs[n * XSTRIDE + q * 4]) = v;
    s4.x += v.x; s4.y += v.y; s4.z += v.z; s4.w += v.w;
    float qd = v.x * v.x + v.y * v.y + v.z * v.z + v.w * v.w;
    qd += __shfl_xor_sync(0xffffffffu, qd, 1);
    qd += __shfl_xor_sync(0xffffffffu, qd, 2);
    mloc = fmaxf(mloc, qd);
  }
#pragma unroll
  for (int off = 4; off < 32; off <<= 1) {
    s4.x += __shfl_xor_sync(0xffffffffu, s4.x, off);
    s4.y += __shfl_xor_sync(0xffffffffu, s4.y, off);
    s4.z += __shfl_xor_sync(0xffffffffu, s4.z, off);
    s4.w += __shfl_xor_sync(0xffffffffu, s4.w, off);
    mloc = fmaxf(mloc, __shfl_xor_sync(0xffffffffu, mloc, off));
  }
  if (lane < 4) *reinterpret_cast<float4*>(&sm->wpart[w][lane * 4]) = s4;
  if (lane == 0) sm->wmax[w] = mloc;

  // ---- Load W slices in two layouts ----
#pragma unroll 1
  for (int idx2 = tid; idx2 < 4096; idx2 += THREADS) {  // [ml][d][c]
    int ml = idx2 >> 8, d = (idx2 >> 4) & 15, c = idx2 & 15;
    float val = Wg[d * 512 + (m0 + ml) * 16 + c];
    sm->Wdc[idx2] = val;
    sm->Wcd[ml * 256 + c * 16 + d] = val;
  }
  __syncthreads();

  if (tid < 16) {
    float s = 0.f;
#pragma unroll
    for (int ww = 0; ww < 24; ++ww) s += sm->wpart[ww][tid];
    sm->sumx[tid] = s;
  }
  if (tid == 16) {
    float mx = 0.f;
#pragma unroll
    for (int ww = 0; ww < 24; ++ww) mx = fmaxf(mx, sm->wmax[ww]);
    sm->mxnorm = sqrtf(mx);
  }

  // 24 warps: group = w % 8 (capsule pair), chunk = w / 8 (3 row chunks)
  const int g     = w & 7;
  const int chunk = w >> 3;
  const int mlb   = 2 * g;
  const int rstart = (chunk == 0) ? 0 : (chunk == 1 ? 704 : 1376);
  const int nsteps = (chunk == 0) ? 22 : 21;
  const float* xbase = &sm->xs[(rstart + lane) * XSTRIDE];
  const int XSTEP = 32 * XSTRIDE;

  for (int it = 0; it < 3; ++it) {
    if (it > 0) {
      // ---- fused logit(log2) + EX2 + weighted-sum pass ----
      ull p[2][8], y[2][8], ib[2];
      float Z[2];
#pragma unroll
      for (int c = 0; c < 2; ++c) {
#pragma unroll
        for (int j = 0; j < 8; ++j) {
          p[c][j] = *reinterpret_cast<const ull*>(&sm->Pacc[mlb + c][2 * j]);
          y[c][j] = 0ull;
        }
        ib[c] = packlh(-sm->bnd[mlb + c], 0.f);
        Z[c] = 0.f;
      }
#pragma unroll 2
      for (int s = 0; s < nsteps; ++s) {
        const ulonglong2* xp =
            reinterpret_cast<const ulonglong2*>(xbase + s * XSTEP);
        ulonglong2 q0 = xp[0], q1 = xp[1], q2 = xp[2], q3 = xp[3];
        ull xx[8];
        xx[0] = q0.x; xx[1] = q0.y; xx[2] = q1.x; xx[3] = q1.y;
        xx[4] = q2.x; xx[5] = q2.y; xx[6] = q3.x; xx[7] = q3.y;
#pragma unroll
        for (int c = 0; c < 2; ++c) {
          ull a0 = fma2(xx[0], p[c][0], ib[c]);   // bound pre-folded
          ull a1 = mul2(xx[1], p[c][1]);
#pragma unroll
          for (int j = 1; j < 4; ++j) {
            a0 = fma2(xx[2 * j],     p[c][2 * j],     a0);
            a1 = fma2(xx[2 * j + 1], p[c][2 * j + 1], a1);
          }
          float e = ex2f(hadd2(add2(a0, a1)));
          Z[c] += e;
          ull e2 = pack2(e);
#pragma unroll
          for (int j = 0; j < 8; ++j) y[c][j] = fma2(e2, xx[j], y[c][j]);
        }
      }

      // 3-level warp reduction -> 4 partials (lanes 0..3)
#pragma unroll
      for (int off = 16; off >= 4; off >>= 1) {
#pragma unroll
        for (int c = 0; c < 2; ++c) {
          Z[c] += __shfl_xor_sync(0xffffffffu, Z[c], off);
#pragma unroll
          for (int j = 0; j < 8; ++j)
            y[c][j] = add2(y[c][j], __shfl_xor_sync(0xffffffffu, y[c][j], off));
        }
      }
      if (lane < 4) {
#pragma unroll
        for (int c = 0; c < 2; ++c) {
          sm->partZ[chunk][lane][mlb + c] = Z[c];
#pragma unroll
          for (int j = 0; j < 8; ++j)
            *reinterpret_cast<ull*>(&sm->party[chunk][lane][mlb + c][2 * j]) = y[c][j];
        }
      }
      __syncthreads();

      // ---- stage 1: fold 12 partials per (cap,d) and per cap ----
      if (tid < 256) {
        const int cap = tid >> 4, d = tid & 15;
        float acc = 0.f;
#pragma unroll
        for (int ch = 0; ch < 3; ++ch)
#pragma unroll
          for (int cg = 0; cg < 4; ++cg)
            acc += sm->party[ch][cg][cap][d];
        sm->party[0][0][cap][d] = acc;   // fold in place
      } else if (tid < 272) {
        const int cap = tid - 256;
        float acc = 0.f;
#pragma unroll
        for (int ch = 0; ch < 3; ++ch)
#pragma unroll
          for (int cg = 0; cg < 4; ++cg)
            acc += sm->partZ[ch][cg][cap];
        sm->partZ[0][0][cap] = acc;
      }
    }
    __syncthreads();

    // ---- per-capsule epilogue: s = yW/Z, squash, Pacc += log2e * W v, bound ----
    if (w < 8) {
      const int ml  = w * 2 + (lane >> 4);
      const int idx = lane & 15;
      float Z = (it == 0) ? 2048.f : sm->partZ[0][0][ml];
      float s = 0.f;
#pragma unroll
      for (int d = 0; d < 16; ++d) {
        float yv = (it == 0) ? sm->sumx[d] : sm->party[0][0][ml][d];
        s += yv * sm->Wdc[(ml * 16 + d) * 16 + idx];
      }
      s *= (1.f / Z);
      float nsq = s * s;
#pragma unroll
      for (int off = 1; off < 16; off <<= 1) nsq += __shfl_xor_sync(0xffffffffu, nsq, off);
      float norm = sqrtf(nsq);
      float fac  = nsq / ((1.f + nsq) * (norm + 1e-7f));
      float v    = s * fac;
      if (it == 2) {
        Y[(size_t)b * 512 + (m0 + ml) * 16 + idx] = v;
      } else {
        sm->vbuf[ml][idx] = v;
        __syncwarp();
        float pd = 0.f;
#pragma unroll
        for (int c = 0; c < 16; ++c)
          pd += sm->Wcd[(ml * 16 + c) * 16 + idx] * sm->vbuf[ml][c];
        float pn = sm->Pacc[ml][idx] + LOG2E * pd;
        sm->Pacc[ml][idx] = pn;
        float cn = pn * pn;
#pragma unroll
        for (int off = 1; off < 16; off <<= 1) cn += __shfl_xor_sync(0xffffffffu, cn, off);
        if (idx == 0) sm->bnd[ml] = sqrtf(cn) * sm->mxnorm;
      }
    }
    __syncthreads();
  }
}

extern "C" void kernel_launch(void* const* d_in, const int* in_sizes, int n_in,
                              void* d_out, int out_size) {
  (void)in_sizes; (void)n_in; (void)out_size;
  const float* X  = (const float*)d_in[0];   // inputs (64, 2048, 16)
  const float* Wg = (const float*)d_in[1];   // W (16, 32, 16)
  float* Y = (float*)d_out;                  // v (64, 32, 16)
  cudaFuncSetAttribute(caps_routing_kernel,
                       cudaFuncAttributeMaxDynamicSharedMemorySize, (int)sizeof(Smem));
  caps_routing_kernel<<<128, THREADS, sizeof(Smem)>>>(X, Wg, Y);
}

// round 11
// speedup vs baseline: 1.2445x; 1.2445x over previous
#include <cuda_runtime.h>
#include <cstdint>

// CapsuleLayer dynamic routing, algebraically collapsed:
//   b[n,m] = x[n,:] @ Pacc[:,m]   (Pacc accumulates log2e * W@v across iterations)
//   s[m,:] = (1/Z) (e^T x) W[:,m,:],  v = squash(s),  Pacc[:,m] += log2e*W[:,m,:] v
// u_hat (268MB) never materialized. Softmax stabilized by Cauchy-Schwarz bound
// |l| <= max_n||x_n|| * ||Pacc_col||, in log2 domain so exp = single EX2.
// R11 (= R10 + cstdint fix): capsule-quarter split -> grid 256 (b x mq, 8 caps
//      each), 256 threads, 2 independent CTAs per SM (RF-exact: 2x256x128) so
//      one block's compute fills the other's stall/barrier windows. x streamed
//      in 4x512-row tiles, double-buffered cp.async (X is L2-resident).

#define NROW    2048
#define DIN     16
#define XSTRIDE 20
#define TILE    512
#define THREADS 256
#define LOG2E   1.4426950408889634f

typedef unsigned long long ull;

struct Smem {
  float xs[2][TILE * XSTRIDE];  // double-buffered x tiles (40KB each)
  float Wdc[8 * 16 * 16];       // [ml][d][c]
  float Wcd[8 * 16 * 16];       // [ml][c][d]
  float Pacc[8][16];            // [ml][d]  (scaled by log2e)
  float party[2][4][8][16];     // [rh][lanegrp][cap][d]
  float partZ[2][4][8];         // [rh][lanegrp][cap]
  float yfull[8][16];
  float Zfull[8];
  float wpart[8][16];           // per-warp partial column sums of x
  float wmax[8];                // per-warp max row-norm^2
  float sumx[16];               // sum over n of x[n,d]
  float vbuf[8][16];            // [ml][c]
  float bnd[8];                 // softmax shift bound (log2 domain)
  float mxnorm;
  float pad[3];
};

__device__ __forceinline__ ull mul2(ull a, ull b) {
  ull d; asm("mul.rn.f32x2 %0, %1, %2;" : "=l"(d) : "l"(a), "l"(b)); return d;
}
__device__ __forceinline__ ull add2(ull a, ull b) {
  ull d; asm("add.rn.f32x2 %0, %1, %2;" : "=l"(d) : "l"(a), "l"(b)); return d;
}
__device__ __forceinline__ ull fma2(ull a, ull b, ull c) {
  ull d; asm("fma.rn.f32x2 %0, %1, %2, %3;" : "=l"(d) : "l"(a), "l"(b), "l"(c)); return d;
}
__device__ __forceinline__ ull pack2(float x) {
  ull d; asm("mov.b64 %0, {%1, %1};" : "=l"(d) : "f"(x)); return d;
}
__device__ __forceinline__ ull packlh(float lo, float hi) {
  ull d; asm("mov.b64 %0, {%1, %2};" : "=l"(d) : "f"(lo), "f"(hi)); return d;
}
__device__ __forceinline__ float hadd2(ull a) {
  float lo, hi; asm("mov.b64 {%0, %1}, %2;" : "=f"(lo), "=f"(hi) : "l"(a)); return lo + hi;
}
__device__ __forceinline__ float ex2f(float x) {
  float r; asm("ex2.approx.f32 %0, %1;" : "=f"(r) : "f"(x)); return r;
}
__device__ __forceinline__ void cp16(unsigned int dst, const void* src) {
  asm volatile("cp.async.ca.shared.global [%0], [%1], 16;" :: "r"(dst), "l"(src));
}
__device__ __forceinline__ void cp_commit() {
  asm volatile("cp.async.commit_group;");
}
__device__ __forceinline__ void cp_wait1() {
  asm volatile("cp.async.wait_group 1;" ::: "memory");
}
__device__ __forceinline__ void cp_wait0() {
  asm volatile("cp.async.wait_group 0;" ::: "memory");
}

__global__ void __launch_bounds__(THREADS, 2)
caps_routing_kernel(const float* __restrict__ X, const float* __restrict__ Wg,
                    float* __restrict__ Y) {
  extern __shared__ char smraw[];
  Smem* sm = reinterpret_cast<Smem*>(smraw);
  const int tid  = threadIdx.x;
  const int lane = tid & 31;
  const int w    = tid >> 5;
  const int b    = blockIdx.x >> 2;
  const int mq   = blockIdx.x & 3;
  const int m0   = mq * 8;

  if (tid < 128) ((float*)sm->Pacc)[tid] = 0.f;
  if (tid < 8)   sm->bnd[tid] = 0.f;

  // ---- W slices (8 caps) in two layouts ----
#pragma unroll
  for (int i = 0; i < 8; ++i) {
    int idx2 = tid + THREADS * i;        // [ml][d][c], 2048 entries
    int ml = idx2 >> 8, d = (idx2 >> 4) & 15, c = idx2 & 15;
    float val = Wg[d * 512 + (m0 + ml) * 16 + c];
    sm->Wdc[idx2] = val;
    sm->Wcd[ml * 256 + c * 16 + d] = val;
  }

  // ---- Phase A: stream X_b once for column sums + max row norm ----
  const float4* Xb = reinterpret_cast<const float4*>(X + (size_t)b * NROW * DIN);
  float4 s4 = make_float4(0.f, 0.f, 0.f, 0.f);
  float mloc = 0.f;
#pragma unroll 4
  for (int i = 0; i < 32; ++i) {
    int idx = tid + THREADS * i;
    float4 v = Xb[idx];
    s4.x += v.x; s4.y += v.y; s4.z += v.z; s4.w += v.w;
    float qd = v.x * v.x + v.y * v.y + v.z * v.z + v.w * v.w;
    qd += __shfl_xor_sync(0xffffffffu, qd, 1);
    qd += __shfl_xor_sync(0xffffffffu, qd, 2);   // full row norm^2 (4 lanes/row)
    mloc = fmaxf(mloc, qd);
  }
#pragma unroll
  for (int off = 4; off < 32; off <<= 1) {
    s4.x += __shfl_xor_sync(0xffffffffu, s4.x, off);
    s4.y += __shfl_xor_sync(0xffffffffu, s4.y, off);
    s4.z += __shfl_xor_sync(0xffffffffu, s4.z, off);
    s4.w += __shfl_xor_sync(0xffffffffu, s4.w, off);
    mloc = fmaxf(mloc, __shfl_xor_sync(0xffffffffu, mloc, off));
  }
  if (lane < 4) *reinterpret_cast<float4*>(&sm->wpart[w][lane * 4]) = s4;
  if (lane == 0) sm->wmax[w] = mloc;
  __syncthreads();

  if (tid < 16) {
    float s = 0.f;
#pragma unroll
    for (int ww = 0; ww < 8; ++ww) s += sm->wpart[ww][tid];
    sm->sumx[tid] = s;
  }
  if (tid == 16) {
    float mx = 0.f;
#pragma unroll
    for (int ww = 0; ww < 8; ++ww) mx = fmaxf(mx, sm->wmax[ww]);
    sm->mxnorm = sqrtf(mx);
  }
  __syncthreads();

  // ---- it0 epilogue (uniform softmax): s = sumx*W/2048 ----
  if (w < 4) {
    const int ml  = w * 2 + (lane >> 4);
    const int idx = lane & 15;
    float s = 0.f;
#pragma unroll
    for (int d = 0; d < 16; ++d)
      s += sm->sumx[d] * sm->Wdc[(ml * 16 + d) * 16 + idx];
    s *= (1.f / 2048.f);
    float nsq = s * s;
#pragma unroll
    for (int off = 1; off < 16; off <<= 1) nsq += __shfl_xor_sync(0xffffffffu, nsq, off);
    float norm = sqrtf(nsq);
    float v = s * (nsq / ((1.f + nsq) * (norm + 1e-7f)));
    sm->vbuf[ml][idx] = v;
    __syncwarp();
    float pd = 0.f;
#pragma unroll
    for (int c = 0; c < 16; ++c)
      pd += sm->Wcd[(ml * 16 + c) * 16 + idx] * sm->vbuf[ml][c];
    float pn = LOG2E * pd;
    sm->Pacc[ml][idx] = pn;
    float cn = pn * pn;
#pragma unroll
    for (int off = 1; off < 16; off <<= 1) cn += __shfl_xor_sync(0xffffffffu, cn, off);
    if (idx == 0) sm->bnd[ml] = sqrtf(cn) * sm->mxnorm;
  }
  __syncthreads();

  const int cp = w & 3;        // capsule pair within the 8
  const int rh = w >> 2;       // row half of each tile
  const int mlb = 2 * cp;
  const int q16 = (tid & 3) * 16;
  const char* Xc = reinterpret_cast<const char*>(Xb);
  unsigned int xs_u32[2];
  xs_u32[0] = (unsigned int)__cvta_generic_to_shared(&sm->xs[0][0]);
  xs_u32[1] = (unsigned int)__cvta_generic_to_shared(&sm->xs[1][0]);

  for (int it = 1; it <= 2; ++it) {
    // prologue: tile 0 -> buf 0
    {
      const char* src = Xc;
#pragma unroll
      for (int i = 0; i < 8; ++i) {
        int idx = tid + THREADS * i;
        cp16(xs_u32[0] + (idx >> 2) * 80 + q16, src + idx * 16);
      }
      cp_commit();
    }
    ull p[2][8], y[2][8], ib[2];
    float Z[2];
#pragma unroll
    for (int c = 0; c < 2; ++c) {
#pragma unroll
      for (int j = 0; j < 8; ++j) {
        p[c][j] = *reinterpret_cast<const ull*>(&sm->Pacc[mlb + c][2 * j]);
        y[c][j] = 0ull;
      }
      ib[c] = packlh(-sm->bnd[mlb + c], 0.f);
      Z[c] = 0.f;
    }

#pragma unroll 1
    for (int t = 0; t < 4; ++t) {
      if (t < 3) {
        const char* src = Xc + (size_t)(t + 1) * TILE * 64;
        unsigned int dbuf = xs_u32[(t + 1) & 1];
#pragma unroll
        for (int i = 0; i < 8; ++i) {
          int idx = tid + THREADS * i;
          cp16(dbuf + (idx >> 2) * 80 + q16, src + idx * 16);
        }
        cp_commit();
        cp_wait1();
      } else {
        cp_wait0();
      }
      __syncthreads();   // tile t ready everywhere

      const float* xbase = &sm->xs[t & 1][(rh * 256 + lane) * XSTRIDE];
#pragma unroll 2
      for (int s = 0; s < 8; ++s) {
        const ulonglong2* xp =
            reinterpret_cast<const ulonglong2*>(xbase + s * (32 * XSTRIDE));
        ulonglong2 q0 = xp[0], q1 = xp[1], q2 = xp[2], q3 = xp[3];
        ull xx[8];
        xx[0] = q0.x; xx[1] = q0.y; xx[2] = q1.x; xx[3] = q1.y;
        xx[4] = q2.x; xx[5] = q2.y; xx[6] = q3.x; xx[7] = q3.y;
#pragma unroll
        for (int c = 0; c < 2; ++c) {
          ull a0 = fma2(xx[0], p[c][0], ib[c]);   // bound pre-folded
          ull a1 = mul2(xx[1], p[c][1]);
#pragma unroll
          for (int j = 1; j < 4; ++j) {
            a0 = fma2(xx[2 * j],     p[c][2 * j],     a0);
            a1 = fma2(xx[2 * j + 1], p[c][2 * j + 1], a1);
          }
          float e = ex2f(hadd2(add2(a0, a1)));
          Z[c] += e;
          ull e2 = pack2(e);
#pragma unroll
          for (int j = 0; j < 8; ++j) y[c][j] = fma2(e2, xx[j], y[c][j]);
        }
      }
      __syncthreads();   // tile t consumed; buffer free for t+2's load
    }

    // 3-level warp reduction -> 4 partials (lanes 0..3)
#pragma unroll
    for (int off = 16; off >= 4; off >>= 1) {
#pragma unroll
      for (int c = 0; c < 2; ++c) {
        Z[c] += __shfl_xor_sync(0xffffffffu, Z[c], off);
#pragma unroll
        for (int j = 0; j < 8; ++j)
          y[c][j] = add2(y[c][j], __shfl_xor_sync(0xffffffffu, y[c][j], off));
      }
    }
    if (lane < 4) {
#pragma unroll
      for (int c = 0; c < 2; ++c) {
        sm->partZ[rh][lane][mlb + c] = Z[c];
#pragma unroll
        for (int j = 0; j < 8; ++j)
          *reinterpret_cast<ull*>(&sm->party[rh][lane][mlb + c][2 * j]) = y[c][j];
      }
    }
    __syncthreads();

    // stage 1: fold 8 partials per (cap,d) and per cap
    if (tid < 128) {
      const int cap = tid >> 4, d = tid & 15;
      float acc = 0.f;
#pragma unroll
      for (int r2 = 0; r2 < 2; ++r2)
#pragma unroll
        for (int cg = 0; cg < 4; ++cg)
          acc += sm->party[r2][cg][cap][d];
      sm->yfull[cap][d] = acc;
    } else if (tid < 136) {
      const int cap = tid - 128;
      float acc = 0.f;
#pragma unroll
      for (int r2 = 0; r2 < 2; ++r2)
#pragma unroll
        for (int cg = 0; cg < 4; ++cg)
          acc += sm->partZ[r2][cg][cap];
      sm->Zfull[cap] = acc;
    }
    __syncthreads();

    // epilogue: s = yW/Z, squash; update Pacc or write Y
    if (w < 4) {
      const int ml  = w * 2 + (lane >> 4);
      const int idx = lane & 15;
      float Zc = sm->Zfull[ml];
      float s = 0.f;
#pragma unroll
      for (int d = 0; d < 16; ++d)
        s += sm->yfull[ml][d] * sm->Wdc[(ml * 16 + d) * 16 + idx];
      s *= (1.f / Zc);
      float nsq = s * s;
#pragma unroll
      for (int off = 1; off < 16; off <<= 1) nsq += __shfl_xor_sync(0xffffffffu, nsq, off);
      float norm = sqrtf(nsq);
      float v = s * (nsq / ((1.f + nsq) * (norm + 1e-7f)));
      if (it == 2) {
        Y[(size_t)b * 512 + (m0 + ml) * 16 + idx] = v;
      } else {
        sm->vbuf[ml][idx] = v;
        __syncwarp();
        float pd = 0.f;
#pragma unroll
        for (int c = 0; c < 16; ++c)
          pd += sm->Wcd[(ml * 16 + c) * 16 + idx] * sm->vbuf[ml][c];
        float pn = sm->Pacc[ml][idx] + LOG2E * pd;
        sm->Pacc[ml][idx] = pn;
        float cn = pn * pn;
#pragma unroll
        for (int off = 1; off < 16; off <<= 1) cn += __shfl_xor_sync(0xffffffffu, cn, off);
        if (idx == 0) sm->bnd[ml] = sqrtf(cn) * sm->mxnorm;
      }
    }
    __syncthreads();
  }
}

extern "C" void kernel_launch(void* const* d_in, const int* in_sizes, int n_in,
                              void* d_out, int out_size) {
  (void)in_sizes; (void)n_in; (void)out_size;
  const float* X  = (const float*)d_in[0];   // inputs (64, 2048, 16)
  const float* Wg = (const float*)d_in[1];   // W (16, 32, 16)
  float* Y = (float*)d_out;                  // v (64, 32, 16)
  cudaFuncSetAttribute(caps_routing_kernel,
                       cudaFuncAttributeMaxDynamicSharedMemorySize, (int)sizeof(Smem));
  caps_routing_kernel<<<256, THREADS, sizeof(Smem)>>>(X, Wg, Y);
}

// round 12
// speedup vs baseline: 2.1967x; 1.7652x over previous
#include <cuda_runtime.h>
#include <cuda_fp16.h>
#include <cstdint>

// CapsuleLayer dynamic routing, algebraically collapsed:
//   b[n,m] = x[n,:] @ Pacc[:,m]   (Pacc accumulates log2e * W@v across iterations)
//   s[m,:] = (1/Z) (e^T x) W[:,m,:],  v = squash(s),  Pacc[:,m] += log2e*W[:,m,:] v
// u_hat (268MB) never materialized. Softmax stabilized by Cauchy-Schwarz bound
// |l| <= max_n||x_n|| * ||Pacc_col||, in log2 domain so exp = single EX2.
// R12: x stored in smem as FP16 (half the LDS/STS crossbar traffic) on the
//      proven C=2/512-thread/16-warp shape. Row stride 24 halves (48B):
//      16B-aligned rows, conflict-free (banks 12*l mod 32 distinct).
//      fp32 math throughout (fp16 only as the storage format of x).

#define NROW    2048
#define DIN     16
#define XSH     24            // halves per row (48B stride)
#define THREADS 512
#define LOG2E   1.4426950408889634f

typedef unsigned long long ull;

struct Smem {
  __half xs[NROW * XSH];        // fp16 x rows, 96KB
  float Wdc[16 * 16 * 16];      // [ml][d][c]
  float Wcd[16 * 16 * 16];      // [ml][c][d]
  float Pacc[16][16];           // [ml][d]  (scaled by log2e)
  float party[2][4][16][16];    // [chunk][lanegrp][ml][d]
  float partZ[2][4][16];        // [chunk][lanegrp][ml]
  float wpart[16][16];          // per-warp partial column sums of x
  float wmax[16];               // per-warp max row-norm^2
  float sumx[16];               // sum over n of x[n,d]
  float vbuf[16][16];           // [ml][c]
  float bnd[16];                // softmax shift bound per ml (log2 domain)
  float mxnorm;
  float pad[3];
};

__device__ __forceinline__ ull mul2(ull a, ull b) {
  ull d; asm("mul.rn.f32x2 %0, %1, %2;" : "=l"(d) : "l"(a), "l"(b)); return d;
}
__device__ __forceinline__ ull add2(ull a, ull b) {
  ull d; asm("add.rn.f32x2 %0, %1, %2;" : "=l"(d) : "l"(a), "l"(b)); return d;
}
__device__ __forceinline__ ull fma2(ull a, ull b, ull c) {
  ull d; asm("fma.rn.f32x2 %0, %1, %2, %3;" : "=l"(d) : "l"(a), "l"(b), "l"(c)); return d;
}
__device__ __forceinline__ ull pack2(float x) {
  ull d; asm("mov.b64 %0, {%1, %1};" : "=l"(d) : "f"(x)); return d;
}
__device__ __forceinline__ ull packlh(float lo, float hi) {
  ull d; asm("mov.b64 %0, {%1, %2};" : "=l"(d) : "f"(lo), "f"(hi)); return d;
}
__device__ __forceinline__ float hadd2(ull a) {
  float lo, hi; asm("mov.b64 {%0, %1}, %2;" : "=f"(lo), "=f"(hi) : "l"(a)); return lo + hi;
}
__device__ __forceinline__ float ex2f(float x) {
  float r; asm("ex2.approx.f32 %0, %1;" : "=f"(r) : "f"(x)); return r;
}
// half2 (as u32) -> packed f32x2 operand
__device__ __forceinline__ ull h2tof2(unsigned int u) {
  float lo, hi;
  asm("{\n\t.reg .f16 h0, h1;\n\t"
      "mov.b32 {h0, h1}, %2;\n\t"
      "cvt.f32.f16 %0, h0;\n\t"
      "cvt.f32.f16 %1, h1;\n\t}"
      : "=f"(lo), "=f"(hi) : "r"(u));
  return packlh(lo, hi);
}

__global__ void __launch_bounds__(THREADS, 1)
caps_routing_kernel(const float* __restrict__ X, const float* __restrict__ Wg,
                    float* __restrict__ Y) {
  extern __shared__ char smraw[];
  Smem* sm = reinterpret_cast<Smem*>(smraw);
  const int tid  = threadIdx.x;
  const int lane = tid & 31;
  const int w    = tid >> 5;
  const int b    = blockIdx.x >> 1;
  const int m0   = (blockIdx.x & 1) * 16;

  if (tid < 256) ((float*)sm->Pacc)[tid] = 0.f;
  if (tid < 16)  sm->bnd[tid] = 0.f;

  // ---- Load x tile; convert to fp16 smem; fold in column sums + max row norm ----
  const float4* Xb = reinterpret_cast<const float4*>(X + (size_t)b * NROW * DIN);
  const int q = tid & 3;
  float4 s4 = make_float4(0.f, 0.f, 0.f, 0.f);
  float mloc = 0.f;
#pragma unroll
  for (int i = 0; i < 16; ++i) {
    int idx = tid + THREADS * i;
    int n = idx >> 2;
    float4 v = Xb[idx];
    __half2 h01 = __floats2half2_rn(v.x, v.y);
    __half2 h23 = __floats2half2_rn(v.z, v.w);
    ull packed;
    asm("mov.b64 %0, {%1, %2};" : "=l"(packed)
        : "r"(*(unsigned int*)&h01), "r"(*(unsigned int*)&h23));
    *reinterpret_cast<ull*>(&sm->xs[n * XSH + q * 4]) = packed;
    s4.x += v.x; s4.y += v.y; s4.z += v.z; s4.w += v.w;
    float qd = v.x * v.x + v.y * v.y + v.z * v.z + v.w * v.w;
    qd += __shfl_xor_sync(0xffffffffu, qd, 1);
    qd += __shfl_xor_sync(0xffffffffu, qd, 2);   // full row norm^2 (4 lanes/row)
    mloc = fmaxf(mloc, qd);
  }
#pragma unroll
  for (int off = 4; off < 32; off <<= 1) {
    s4.x += __shfl_xor_sync(0xffffffffu, s4.x, off);
    s4.y += __shfl_xor_sync(0xffffffffu, s4.y, off);
    s4.z += __shfl_xor_sync(0xffffffffu, s4.z, off);
    s4.w += __shfl_xor_sync(0xffffffffu, s4.w, off);
    mloc = fmaxf(mloc, __shfl_xor_sync(0xffffffffu, mloc, off));
  }
  if (lane < 4) *reinterpret_cast<float4*>(&sm->wpart[w][lane * 4]) = s4;
  if (lane == 0) sm->wmax[w] = mloc;

  // ---- Load W slices in two layouts ----
#pragma unroll
  for (int i = 0; i < 8; ++i) {
    int idx2 = tid + THREADS * i;         // [ml][d][c]
    int ml = idx2 >> 8, d = (idx2 >> 4) & 15, c = idx2 & 15;
    float val = Wg[d * 512 + (m0 + ml) * 16 + c];
    sm->Wdc[idx2] = val;
    sm->Wcd[ml * 256 + c * 16 + d] = val;
  }
  __syncthreads();

  if (tid < 16) {
    float s = 0.f;
#pragma unroll
    for (int ww = 0; ww < 16; ++ww) s += sm->wpart[ww][tid];
    sm->sumx[tid] = s;
  }
  if (tid == 16) {
    float mx = 0.f;
#pragma unroll
    for (int ww = 0; ww < 16; ++ww) mx = fmaxf(mx, sm->wmax[ww]);
    sm->mxnorm = sqrtf(mx);
  }

  const int g     = w & 7;        // capsule pair group
  const int chunk = w >> 3;       // row chunk (0: 0-1023, 1: 1024-2047)
  const int mlb   = 2 * g;
  const __half* xbase = &sm->xs[(chunk * 1024 + lane) * XSH];
  const int XSTEP = 32 * XSH;     // halves per step stride

  for (int it = 0; it < 3; ++it) {
    if (it > 0) {
      // ---- fused logit(log2) + EX2 + weighted-sum pass (fp16-x storage) ----
      ull p[2][8], y[2][8], ib[2];
      float Z[2];
#pragma unroll
      for (int c = 0; c < 2; ++c) {
#pragma unroll
        for (int j = 0; j < 8; ++j) {
          p[c][j] = *reinterpret_cast<const ull*>(&sm->Pacc[mlb + c][2 * j]);
          y[c][j] = 0ull;
        }
        ib[c] = packlh(-sm->bnd[mlb + c], 0.f);
        Z[c] = 0.f;
      }
#pragma unroll 2
      for (int s = 0; s < 32; ++s) {
        const uint4* xp = reinterpret_cast<const uint4*>(xbase + s * XSTEP);
        uint4 a = xp[0];       // halves 0-7
        uint4 bq = xp[1];      // halves 8-15
        ull xx[8];
        xx[0] = h2tof2(a.x);  xx[1] = h2tof2(a.y);
        xx[2] = h2tof2(a.z);  xx[3] = h2tof2(a.w);
        xx[4] = h2tof2(bq.x); xx[5] = h2tof2(bq.y);
        xx[6] = h2tof2(bq.z); xx[7] = h2tof2(bq.w);
#pragma unroll
        for (int c = 0; c < 2; ++c) {
          ull a0 = fma2(xx[0], p[c][0], ib[c]);   // bound pre-folded
          ull a1 = mul2(xx[1], p[c][1]);
#pragma unroll
          for (int j = 1; j < 4; ++j) {
            a0 = fma2(xx[2 * j],     p[c][2 * j],     a0);
            a1 = fma2(xx[2 * j + 1], p[c][2 * j + 1], a1);
          }
          float e = ex2f(hadd2(add2(a0, a1)));
          Z[c] += e;
          ull e2 = pack2(e);
#pragma unroll
          for (int j = 0; j < 8; ++j) y[c][j] = fma2(e2, xx[j], y[c][j]);
        }
      }

      // 3-level warp reduction -> 4 partials (lanes 0..3)
#pragma unroll
      for (int off = 16; off >= 4; off >>= 1) {
#pragma unroll
        for (int c = 0; c < 2; ++c) {
          Z[c] += __shfl_xor_sync(0xffffffffu, Z[c], off);
#pragma unroll
          for (int j = 0; j < 8; ++j)
            y[c][j] = add2(y[c][j], __shfl_xor_sync(0xffffffffu, y[c][j], off));
        }
      }
      if (lane < 4) {
#pragma unroll
        for (int c = 0; c < 2; ++c) {
          sm->partZ[chunk][lane][mlb + c] = Z[c];
#pragma unroll
          for (int j = 0; j < 8; ++j)
            *reinterpret_cast<ull*>(&sm->party[chunk][lane][mlb + c][2 * j]) = y[c][j];
        }
      }
    }
    __syncthreads();

    // ---- per-capsule epilogue: s = yW/Z, squash, Pacc += log2e * W v, bound ----
    if (w < 8) {
      const int ml  = w * 2 + (lane >> 4);
      const int idx = lane & 15;
      float Z, yv;
      if (it == 0) {
        Z = 2048.f;
      } else {
        Z = 0.f;
#pragma unroll
        for (int cg = 0; cg < 4; ++cg) Z += sm->partZ[0][cg][ml] + sm->partZ[1][cg][ml];
      }
      float s = 0.f;
#pragma unroll
      for (int d = 0; d < 16; ++d) {
        if (it == 0) {
          yv = sm->sumx[d];
        } else {
          yv = 0.f;
#pragma unroll
          for (int cg = 0; cg < 4; ++cg)
            yv += sm->party[0][cg][ml][d] + sm->party[1][cg][ml][d];
        }
        s += yv * sm->Wdc[(ml * 16 + d) * 16 + idx];
      }
      s *= (1.f / Z);
      float nsq = s * s;
#pragma unroll
      for (int off = 1; off < 16; off <<= 1) nsq += __shfl_xor_sync(0xffffffffu, nsq, off);
      float norm = sqrtf(nsq);
      float fac  = nsq / ((1.f + nsq) * (norm + 1e-7f));
      float v    = s * fac;
      if (it == 2) {
        Y[(size_t)b * 512 + (m0 + ml) * 16 + idx] = v;
      } else {
        sm->vbuf[ml][idx] = v;
        __syncwarp();
        float pd = 0.f;
#pragma unroll
        for (int c = 0; c < 16; ++c)
          pd += sm->Wcd[(ml * 16 + c) * 16 + idx] * sm->vbuf[ml][c];
        float pn = sm->Pacc[ml][idx] + LOG2E * pd;
        sm->Pacc[ml][idx] = pn;
        float cn = pn * pn;
#pragma unroll
        for (int off = 1; off < 16; off <<= 1) cn += __shfl_xor_sync(0xffffffffu, cn, off);
        if (idx == 0) sm->bnd[ml] = sqrtf(cn) * sm->mxnorm;
      }
    }
    __syncthreads();
  }
}

extern "C" void kernel_launch(void* const* d_in, const int* in_sizes, int n_in,
                              void* d_out, int out_size) {
  (void)in_sizes; (void)n_in; (void)out_size;
  const float* X  = (const float*)d_in[0];   // inputs (64, 2048, 16)
  const float* Wg = (const float*)d_in[1];   // W (16, 32, 16)
  float* Y = (float*)d_out;                  // v (64, 32, 16)
  cudaFuncSetAttribute(caps_routing_kernel,
                       cudaFuncAttributeMaxDynamicSharedMemorySize, (int)sizeof(Smem));
  caps_routing_kernel<<<128, THREADS, sizeof(Smem)>>>(X, Wg, Y);
}

// round 13
// speedup vs baseline: 5.0652x; 2.3058x over previous
#include <cuda_runtime.h>
#include <cuda_fp16.h>
#include <cstdint>

// CapsuleLayer dynamic routing, algebraically collapsed (u_hat never built):
//   L[n,m] = x[n,:] @ Pacc[:,m]  (Pacc = log2e * accum W@v, so exp == EX2)
//   E = 2^(L - bnd + 15), Z[m] = sum_n E, y[m,:] = E^T x
//   s = (y/Z) W, v = squash(s), Pacc += log2e W v
// bnd = Cauchy-Schwarz bound ||Pacc_col||*max||x_n||; +15 shift keeps fp16 E
// in range (e <= 2^15 < 65504; dropped tail < 2^-19 of max).
// R13: both GEMMs on tensor cores (mma.m16n8k16 f16->f32), flash-attn C->A
// fragment reuse for E, P split hi+lo fp16 for full logit precision.

#define NROW    2048
#define XSH     24            // halves per x row (48B: 16B-aligned, conflict-free)
#define THREADS 512
#define LOG2E   1.4426950408889634f

typedef unsigned long long ull;
typedef unsigned int uint;

struct Smem {
  __half xs[NROW * XSH];        // fp16 x rows, 96KB
  float  Wdc[4096];             // [ml][d][c]
  float  Wcd[4096];             // [ml][c][d]
  float  Pacc[16][16];          // fp32 master (log2e-scaled)
  __half Pt_hi[16][XSH];        // P^T fp16 high part  [cap][d]
  __half Pt_lo[16][XSH];        // P^T fp16 residual
  float  party[16][16][16];     // [warp][cap][d] partial y
  float  partZ[16][16];         // [warp][cap]
  float  yfull[16][16];
  float  Zfull[16];
  float  wpart[16][16];
  float  wmax[16];
  float  sumx[16];
  float  vbuf[16][16];
  float  bnd[16];               // log2-domain bound per cap
  float  mxnorm;
  float  pad[3];
};

__device__ __forceinline__ float ex2f(float x) {
  float r; asm("ex2.approx.f32 %0, %1;" : "=f"(r) : "f"(x)); return r;
}
// pack two f32 -> f16x2 (lo = second operand)
__device__ __forceinline__ uint cvt2h(float hi, float lo) {
  uint r; asm("cvt.rn.f16x2.f32 %0, %1, %2;" : "=r"(r) : "f"(hi), "f"(lo)); return r;
}
__device__ __forceinline__ void hmma(float& d0, float& d1, float& d2, float& d3,
                                     uint a0, uint a1, uint a2, uint a3,
                                     uint b0, uint b1) {
  asm("mma.sync.aligned.m16n8k16.row.col.f32.f16.f16.f32 "
      "{%0,%1,%2,%3}, {%4,%5,%6,%7}, {%8,%9}, {%0,%1,%2,%3};"
      : "+f"(d0), "+f"(d1), "+f"(d2), "+f"(d3)
      : "r"(a0), "r"(a1), "r"(a2), "r"(a3), "r"(b0), "r"(b1));
}
__device__ __forceinline__ void ldsm4t(uint& r0, uint& r1, uint& r2, uint& r3,
                                       uint addr) {
  asm volatile("ldmatrix.sync.aligned.m8n8.x4.trans.shared.b16 {%0,%1,%2,%3}, [%4];"
               : "=r"(r0), "=r"(r1), "=r"(r2), "=r"(r3) : "r"(addr));
}

__global__ void __launch_bounds__(THREADS, 1)
caps_routing_kernel(const float* __restrict__ X, const float* __restrict__ Wg,
                    float* __restrict__ Y) {
  extern __shared__ char smraw[];
  Smem* sm = reinterpret_cast<Smem*>(smraw);
  const int tid  = threadIdx.x;
  const int lane = tid & 31;
  const int w    = tid >> 5;
  const int b    = blockIdx.x >> 1;
  const int m0   = (blockIdx.x & 1) * 16;

  if (tid < 256) ((float*)sm->Pacc)[tid] = 0.f;
  if (tid < 16)  sm->bnd[tid] = 0.f;

  // ---- Load x tile; fp16 into smem; fold in column sums + max row norm ----
  const float4* Xb = reinterpret_cast<const float4*>(X + (size_t)b * NROW * 16);
  const int q = tid & 3;
  float4 s4 = make_float4(0.f, 0.f, 0.f, 0.f);
  float mloc = 0.f;
#pragma unroll
  for (int i = 0; i < 16; ++i) {
    int idx = tid + THREADS * i;
    int n = idx >> 2;
    float4 v = Xb[idx];
    __half2 h01 = __floats2half2_rn(v.x, v.y);
    __half2 h23 = __floats2half2_rn(v.z, v.w);
    ull packed;
    asm("mov.b64 %0, {%1, %2};" : "=l"(packed)
        : "r"(*(uint*)&h01), "r"(*(uint*)&h23));
    *reinterpret_cast<ull*>(&sm->xs[n * XSH + q * 4]) = packed;
    s4.x += v.x; s4.y += v.y; s4.z += v.z; s4.w += v.w;
    float qd = v.x * v.x + v.y * v.y + v.z * v.z + v.w * v.w;
    qd += __shfl_xor_sync(0xffffffffu, qd, 1);
    qd += __shfl_xor_sync(0xffffffffu, qd, 2);
    mloc = fmaxf(mloc, qd);
  }
#pragma unroll
  for (int off = 4; off < 32; off <<= 1) {
    s4.x += __shfl_xor_sync(0xffffffffu, s4.x, off);
    s4.y += __shfl_xor_sync(0xffffffffu, s4.y, off);
    s4.z += __shfl_xor_sync(0xffffffffu, s4.z, off);
    s4.w += __shfl_xor_sync(0xffffffffu, s4.w, off);
    mloc = fmaxf(mloc, __shfl_xor_sync(0xffffffffu, mloc, off));
  }
  if (lane < 4) *reinterpret_cast<float4*>(&sm->wpart[w][lane * 4]) = s4;
  if (lane == 0) sm->wmax[w] = mloc;

  // ---- W slices in two layouts (fp32, epilogue only) ----
#pragma unroll
  for (int i = 0; i < 8; ++i) {
    int idx2 = tid + THREADS * i;
    int ml = idx2 >> 8, d = (idx2 >> 4) & 15, c = idx2 & 15;
    float val = Wg[d * 512 + (m0 + ml) * 16 + c];
    sm->Wdc[idx2] = val;
    sm->Wcd[ml * 256 + c * 16 + d] = val;
  }
  __syncthreads();

  if (tid < 16) {
    float s = 0.f;
#pragma unroll
    for (int ww = 0; ww < 16; ++ww) s += sm->wpart[ww][tid];
    sm->sumx[tid] = s;
  }
  if (tid == 16) {
    float mx = 0.f;
#pragma unroll
    for (int ww = 0; ww < 16; ++ww) mx = fmaxf(mx, sm->wmax[ww]);
    sm->mxnorm = sqrtf(mx);
  }
  __syncthreads();

  const int gid = lane >> 2, tig = lane & 3;
  const uint xsb = (uint)__cvta_generic_to_shared(sm->xs);
  // ldmatrix.x4.trans lane->address map: 4 8x8 tiles of X[nb..nb+15][0..15]
  const int lrow = (lane & 7) + ((lane >> 4) << 3);
  const int lcol = (lane & 8) ? 16 : 0;

  for (int it = 0; it < 3; ++it) {
    if (it > 0) {
      // ---- tensor-core pass: each warp does 128 rows x all 16 caps ----
      uint pah[4], pal[4];
      pah[0] = *(const uint*)&sm->Pt_hi[gid][2 * tig];
      pah[1] = *(const uint*)&sm->Pt_hi[gid + 8][2 * tig];
      pah[2] = *(const uint*)&sm->Pt_hi[gid][2 * tig + 8];
      pah[3] = *(const uint*)&sm->Pt_hi[gid + 8][2 * tig + 8];
      pal[0] = *(const uint*)&sm->Pt_lo[gid][2 * tig];
      pal[1] = *(const uint*)&sm->Pt_lo[gid + 8][2 * tig];
      pal[2] = *(const uint*)&sm->Pt_lo[gid][2 * tig + 8];
      pal[3] = *(const uint*)&sm->Pt_lo[gid + 8][2 * tig + 8];
      const float iA = 15.f - sm->bnd[gid];
      const float iB = 15.f - sm->bnd[gid + 8];
      float y00 = 0.f, y01 = 0.f, y02 = 0.f, y03 = 0.f;
      float y10 = 0.f, y11 = 0.f, y12 = 0.f, y13 = 0.f;
      float z0 = 0.f, z1 = 0.f;
      const int nb0 = w * 128;
      const uint lm0 = xsb + (uint)(nb0 + lrow) * 48 + lcol;

#pragma unroll 2
      for (int ks = 0; ks < 8; ++ks) {
        const int nb = nb0 + ks * 16;
        // GEMM1 B-frags: X rows (plain b32 reads, conflict-free)
        const uint* xr0 = (const uint*)&sm->xs[(nb + gid) * XSH + 2 * tig];
        const uint* xr1 = (const uint*)&sm->xs[(nb + 8 + gid) * XSH + 2 * tig];
        uint b00 = xr0[0], b01 = xr0[4];
        uint b10 = xr1[0], b11 = xr1[4];
        // GEMM1: logits (caps x n), bnd+15 folded into C init, P = hi + lo
        float c00 = iA, c01 = iA, c02 = iB, c03 = iB;
        hmma(c00, c01, c02, c03, pah[0], pah[1], pah[2], pah[3], b00, b01);
        hmma(c00, c01, c02, c03, pal[0], pal[1], pal[2], pal[3], b00, b01);
        float c10 = iA, c11 = iA, c12 = iB, c13 = iB;
        hmma(c10, c11, c12, c13, pah[0], pah[1], pah[2], pah[3], b10, b11);
        hmma(c10, c11, c12, c13, pal[0], pal[1], pal[2], pal[3], b10, b11);
        // softmax numerators
        float e0 = ex2f(c00), e1 = ex2f(c01), e2 = ex2f(c02), e3 = ex2f(c03);
        float e4 = ex2f(c10), e5 = ex2f(c11), e6 = ex2f(c12), e7 = ex2f(c13);
        z0 += (e0 + e1) + (e4 + e5);
        z1 += (e2 + e3) + (e6 + e7);
        // C-frag -> A-frag of GEMM2 (exact layout match, just cvt to fp16)
        uint a0 = cvt2h(e1, e0), a1 = cvt2h(e3, e2);
        uint a2 = cvt2h(e5, e4), a3 = cvt2h(e7, e6);
        // GEMM2: y[caps,d] += E(caps x 16n) @ X(16n x 16d)
        uint r0, r1, r2, r3;
        ldsm4t(r0, r1, r2, r3, lm0 + (uint)(ks * 16 * 48));
        hmma(y00, y01, y02, y03, a0, a1, a2, a3, r0, r2);   // d 0-7
        hmma(y10, y11, y12, y13, a0, a1, a2, a3, r1, r3);   // d 8-15
      }
      // Z: quad reduce (4 lanes share each cap row)
      z0 += __shfl_xor_sync(0xffffffffu, z0, 1);
      z0 += __shfl_xor_sync(0xffffffffu, z0, 2);
      z1 += __shfl_xor_sync(0xffffffffu, z1, 1);
      z1 += __shfl_xor_sync(0xffffffffu, z1, 2);
      if (tig == 0) {
        sm->partZ[w][gid] = z0;
        sm->partZ[w][gid + 8] = z1;
      }
      *(float2*)&sm->party[w][gid][2 * tig]         = make_float2(y00, y01);
      *(float2*)&sm->party[w][gid + 8][2 * tig]     = make_float2(y02, y03);
      *(float2*)&sm->party[w][gid][2 * tig + 8]     = make_float2(y10, y11);
      *(float2*)&sm->party[w][gid + 8][2 * tig + 8] = make_float2(y12, y13);
      __syncthreads();

      // fold 16 warp partials
      if (tid < 256) {
        const int cap = tid >> 4, d = tid & 15;
        float acc = 0.f;
#pragma unroll
        for (int ww = 0; ww < 16; ++ww) acc += sm->party[ww][cap][d];
        sm->yfull[cap][d] = acc;
      } else if (tid < 272) {
        const int cap = tid - 256;
        float acc = 0.f;
#pragma unroll
        for (int ww = 0; ww < 16; ++ww) acc += sm->partZ[ww][cap];
        sm->Zfull[cap] = acc;
      }
    }
    __syncthreads();

    // ---- epilogue: s = yW/Z, squash, Pacc += log2e W v, Pt hi/lo, bound ----
    if (w < 8) {
      const int ml  = w * 2 + (lane >> 4);
      const int idx = lane & 15;
      float Z = (it == 0) ? 2048.f : sm->Zfull[ml];
      float s = 0.f;
#pragma unroll
      for (int d = 0; d < 16; ++d) {
        float yv = (it == 0) ? sm->sumx[d] : sm->yfull[ml][d];
        s += yv * sm->Wdc[(ml * 16 + d) * 16 + idx];
      }
      s *= (1.f / Z);
      float nsq = s * s;
#pragma unroll
      for (int off = 1; off < 16; off <<= 1) nsq += __shfl_xor_sync(0xffffffffu, nsq, off);
      float norm = sqrtf(nsq);
      float fac  = nsq / ((1.f + nsq) * (norm + 1e-7f));
      float v    = s * fac;
      if (it == 2) {
        Y[(size_t)b * 512 + (m0 + ml) * 16 + idx] = v;
      } else {
        sm->vbuf[ml][idx] = v;
        __syncwarp();
        float pd = 0.f;
#pragma unroll
        for (int c = 0; c < 16; ++c)
          pd += sm->Wcd[(ml * 16 + c) * 16 + idx] * sm->vbuf[ml][c];
        float pn = sm->Pacc[ml][idx] + LOG2E * pd;
        sm->Pacc[ml][idx] = pn;
        __half h = __float2half_rn(pn);
        sm->Pt_hi[ml][idx] = h;
        sm->Pt_lo[ml][idx] = __float2half_rn(pn - __half2float(h));
        float cn = pn * pn;
#pragma unroll
        for (int off = 1; off < 16; off <<= 1) cn += __shfl_xor_sync(0xffffffffu, cn, off);
        if (idx == 0) sm->bnd[ml] = sqrtf(cn) * sm->mxnorm;
      }
    }
    __syncthreads();
  }
}

extern "C" void kernel_launch(void* const* d_in, const int* in_sizes, int n_in,
                              void* d_out, int out_size) {
  (void)in_sizes; (void)n_in; (void)out_size;
  const float* X  = (const float*)d_in[0];   // inputs (64, 2048, 16)
  const float* Wg = (const float*)d_in[1];   // W (16, 32, 16)
  float* Y = (float*)d_out;                  // v (64, 32, 16)
  cudaFuncSetAttribute(caps_routing_kernel,
                       cudaFuncAttributeMaxDynamicSharedMemorySize, (int)sizeof(Smem));
  caps_routing_kernel<<<128, THREADS, sizeof(Smem)>>>(X, Wg, Y);
}